// round 4
// baseline (speedup 1.0000x reference)
#include <cuda_runtime.h>
#include <math.h>

// ---------------------------------------------------------------------------
// Problem constants
// ---------------------------------------------------------------------------
#define SEQ_LEN   8
#define FEAT      2048
#define DOUT      1152
#define WAY       5
#define SHOT      5
#define NQ        500
#define T_LEN     28
#define N_SUP     (WAY * SHOT)           // 25
#define N_CLIPS   (N_SUP + NQ)           // 525
#define N_FRAMES  (N_CLIPS * SEQ_LEN)    // 4200
#define WCOLS     (4 * DOUT)             // 4608 = [k_top | k_bot | v_top | v_bot]
#define SROWS     (N_SUP * T_LEN)        // 700
#define QROWS     (NQ * T_LEN)           // 14000
#define KU        (SHOT * T_LEN)         // 140
#define LN_EPS    1e-5f

__constant__ int2 c_tup[T_LEN] = {
    {0,1},{0,2},{0,3},{0,4},{0,5},{0,6},{0,7},
    {1,2},{1,3},{1,4},{1,5},{1,6},{1,7},
    {2,3},{2,4},{2,5},{2,6},{2,7},
    {3,4},{3,5},{3,6},{3,7},
    {4,5},{4,6},{4,7},
    {5,6},{5,7},
    {6,7}
};

// ---------------------------------------------------------------------------
// Device scratch (allocation-free workaround per harness rules)
// ---------------------------------------------------------------------------
__device__ float g_X[N_FRAMES * FEAT];        // frames + PE          (34.4 MB)
__device__ float g_W[FEAT * WCOLS];           // packed weights       (37.7 MB)
__device__ float g_P[N_FRAMES * WCOLS];       // frame partials       (77.4 MB)
__device__ float g_sk[SROWS * DOUT];          // support K (LN'd)
__device__ float g_sv[SROWS * DOUT];          // support V
__device__ float g_qk[QROWS * DOUT];          // query K (LN'd)      (64.5 MB)
__device__ float g_qv[QROWS * DOUT];          // query V             (64.5 MB)
__device__ float g_S[QROWS * SROWS];          // scores/attn         (39.2 MB)
__device__ float g_dist[WAY * NQ];            // distance accumulators

// ---------------------------------------------------------------------------
// K0a: build X = frames + positional encoding
// layout: row = clip*8 + frame, clips 0..24 support then 25..524 queries
// ---------------------------------------------------------------------------
__global__ void pack_x_kernel(const float* __restrict__ sup,
                              const float* __restrict__ qry)
{
    int idx = blockIdx.x * blockDim.x + threadIdx.x;
    if (idx >= N_FRAMES * FEAT) return;
    int d   = idx & (FEAT - 1);
    int row = idx >> 11;              // FEAT = 2048 = 2^11
    int f   = row & 7;

    // positional encoding (matches numpy float32 computation)
    const float c = -9.210340371976184f / 2048.0f;   // -ln(10000)/d_model
    int  i2  = d >> 1;
    float dv = expf((float)(2 * i2) * c);
    float arg = (float)f * dv;
    float pe  = (d & 1) ? cosf(arg) : sinf(arg);

    float x = (row < N_SUP * SEQ_LEN) ? sup[idx] : qry[idx - N_SUP * SEQ_LEN * FEAT];
    g_X[idx] = x + pe;
}

// ---------------------------------------------------------------------------
// K0b: pack weights into [2048, 4608]: cols {k_top, k_bot, v_top, v_bot}
// ---------------------------------------------------------------------------
__global__ void pack_w_kernel(const float* __restrict__ kw,
                              const float* __restrict__ vw)
{
    int idx = blockIdx.x * blockDim.x + threadIdx.x;
    if (idx >= FEAT * WCOLS) return;
    int k  = idx / WCOLS;
    int jc = idx - k * WCOLS;
    int blk = jc / DOUT;
    int jj  = jc - blk * DOUT;
    const float* src = (blk < 2) ? kw : vw;
    int half = blk & 1;
    g_W[idx] = src[(size_t)(half * FEAT + k) * DOUT + jj];
}

__global__ void zero_dist_kernel()
{
    int idx = blockIdx.x * blockDim.x + threadIdx.x;
    if (idx < WAY * NQ) g_dist[idx] = 0.0f;
}

// ---------------------------------------------------------------------------
// Generic 128x128x8 register-tiled fp32 GEMM.
// BT=0: C[M,N] = A[M,K] (row-major) @ B[K,N] (row-major)
// BT=1: C[M,N] = A[M,K] (row-major) @ B[N,K]^T (row-major, K contiguous)
// K must be a multiple of 8. scale applied at store.
// ---------------------------------------------------------------------------
template<int BT>
__global__ void __launch_bounds__(256)
gemm_tile(const float* __restrict__ A, const float* __restrict__ B,
          float* __restrict__ C, int M, int N, int K,
          int lda, int ldb, int ldc, float scale)
{
    __shared__ float As[8][128];
    __shared__ float Bs[8][128];

    int tid = threadIdx.x;
    int tx  = tid & 15;       // 0..15 -> 8 cols each
    int ty  = tid >> 4;       // 0..15 -> 8 rows each
    int mBase = blockIdx.y * 128;
    int nBase = blockIdx.x * 128;

    float acc[8][8];
#pragma unroll
    for (int i = 0; i < 8; i++)
#pragma unroll
        for (int j = 0; j < 8; j++) acc[i][j] = 0.0f;

    int aRow = tid >> 1;            // 0..127
    int aK   = (tid & 1) * 4;       // 0 or 4

    for (int k0 = 0; k0 < K; k0 += 8) {
        // ---- load A tile (transposed into As[k][m]) ----
        {
            int gr = mBase + aRow;
            if (gr < M) {
                float4 v = *(const float4*)(A + (size_t)gr * lda + k0 + aK);
                As[aK + 0][aRow] = v.x; As[aK + 1][aRow] = v.y;
                As[aK + 2][aRow] = v.z; As[aK + 3][aRow] = v.w;
            } else {
                As[aK + 0][aRow] = 0.f; As[aK + 1][aRow] = 0.f;
                As[aK + 2][aRow] = 0.f; As[aK + 3][aRow] = 0.f;
            }
        }
        // ---- load B tile ----
        if (BT == 0) {
            int bK = tid >> 5;               // 0..7
            int bC = (tid & 31) * 4;         // 0..124
            int gc = nBase + bC;
            const float* p = B + (size_t)(k0 + bK) * ldb + gc;
            if (gc + 3 < N) {
                float4 v = *(const float4*)p;
                Bs[bK][bC + 0] = v.x; Bs[bK][bC + 1] = v.y;
                Bs[bK][bC + 2] = v.z; Bs[bK][bC + 3] = v.w;
            } else {
#pragma unroll
                for (int l = 0; l < 4; l++)
                    Bs[bK][bC + l] = (gc + l < N) ? p[l] : 0.f;
            }
        } else {
            int bN = tid >> 1;
            int bK = (tid & 1) * 4;
            int gn = nBase + bN;
            if (gn < N) {
                float4 v = *(const float4*)(B + (size_t)gn * ldb + k0 + bK);
                Bs[bK + 0][bN] = v.x; Bs[bK + 1][bN] = v.y;
                Bs[bK + 2][bN] = v.z; Bs[bK + 3][bN] = v.w;
            } else {
                Bs[bK + 0][bN] = 0.f; Bs[bK + 1][bN] = 0.f;
                Bs[bK + 2][bN] = 0.f; Bs[bK + 3][bN] = 0.f;
            }
        }
        __syncthreads();

#pragma unroll
        for (int k = 0; k < 8; k++) {
            float ar[8], br[8];
            *(float4*)&ar[0] = *(const float4*)&As[k][ty * 8];
            *(float4*)&ar[4] = *(const float4*)&As[k][ty * 8 + 4];
            *(float4*)&br[0] = *(const float4*)&Bs[k][tx * 8];
            *(float4*)&br[4] = *(const float4*)&Bs[k][tx * 8 + 4];
#pragma unroll
            for (int i = 0; i < 8; i++)
#pragma unroll
                for (int j = 0; j < 8; j++)
                    acc[i][j] += ar[i] * br[j];
        }
        __syncthreads();
    }

#pragma unroll
    for (int i = 0; i < 8; i++) {
        int gr = mBase + ty * 8 + i;
        if (gr >= M) continue;
        float* crow = C + (size_t)gr * ldc;
#pragma unroll
        for (int j = 0; j < 8; j++) {
            int gc = nBase + tx * 8 + j;
            if (gc < N) crow[gc] = acc[i][j] * scale;
        }
    }
}

// ---------------------------------------------------------------------------
// K2: combine frame partials into tuple rows + bias; LN on K path.
// one block per (clip n, tuple t) row.  P columns: [Ak|Bk|Av|Bv]
// ---------------------------------------------------------------------------
__global__ void __launch_bounds__(256)
combine_ln_kernel(const float* __restrict__ kb, const float* __restrict__ vb,
                  const float* __restrict__ gamma, const float* __restrict__ beta)
{
    __shared__ float buf[DOUT];
    __shared__ float rs[8], rq[8];

    int r = blockIdx.x;
    int n = r / T_LEN;
    int t = r - n * T_LEN;
    int2 tp = c_tup[t];

    const float* pi = g_P + (size_t)(n * SEQ_LEN + tp.x) * WCOLS;
    const float* pj = g_P + (size_t)(n * SEQ_LEN + tp.y) * WCOLS;

    float* kout;
    float* vout;
    if (n < N_SUP) {
        kout = g_sk + (size_t)r * DOUT;
        vout = g_sv + (size_t)r * DOUT;
    } else {
        size_t qr = (size_t)(r - SROWS) * DOUT;
        kout = g_qk + qr;
        vout = g_qv + qr;
    }

    int tid = threadIdx.x;
    float s = 0.f, sq = 0.f;
    for (int d = tid; d < DOUT; d += 256) {
        float kv = pi[d] + pj[DOUT + d] + kb[d];
        buf[d] = kv;
        s += kv; sq += kv * kv;
        vout[d] = pi[2 * DOUT + d] + pj[3 * DOUT + d] + vb[d];
    }
#pragma unroll
    for (int o = 16; o; o >>= 1) {
        s  += __shfl_xor_sync(0xffffffffu, s, o);
        sq += __shfl_xor_sync(0xffffffffu, sq, o);
    }
    int lane = tid & 31, wid = tid >> 5;
    if (lane == 0) { rs[wid] = s; rq[wid] = sq; }
    __syncthreads();
    if (tid == 0) {
        float S = 0.f, Q = 0.f;
#pragma unroll
        for (int w = 0; w < 8; w++) { S += rs[w]; Q += rq[w]; }
        rs[0] = S; rq[0] = Q;
    }
    __syncthreads();
    float mean = rs[0] * (1.0f / DOUT);
    float var  = rq[0] * (1.0f / DOUT) - mean * mean;
    float rstd = rsqrtf(var + LN_EPS);
    for (int d = tid; d < DOUT; d += 256)
        kout[d] = (buf[d] - mean) * rstd * gamma[d] + beta[d];
}

// ---------------------------------------------------------------------------
// K4: softmax over 140-chunks.  one warp per (query-tuple row, class).
// ---------------------------------------------------------------------------
__global__ void softmax_kernel()
{
    int warp = (blockIdx.x * blockDim.x + threadIdx.x) >> 5;
    if (warp >= QROWS * WAY) return;
    int lane = threadIdx.x & 31;
    int row = warp / WAY;
    int c   = warp - row * WAY;
    float* p = g_S + (size_t)row * SROWS + c * KU;

    float v[5];
    float mx = -1e30f;
#pragma unroll
    for (int l = 0; l < 5; l++) {
        int idx = lane + 32 * l;
        v[l] = (idx < KU) ? p[idx] : -1e30f;
        mx = fmaxf(mx, v[l]);
    }
#pragma unroll
    for (int o = 16; o; o >>= 1) mx = fmaxf(mx, __shfl_xor_sync(0xffffffffu, mx, o));
    float s = 0.f;
#pragma unroll
    for (int l = 0; l < 5; l++) {
        int idx = lane + 32 * l;
        v[l] = (idx < KU) ? expf(v[l] - mx) : 0.f;
        s += v[l];
    }
#pragma unroll
    for (int o = 16; o; o >>= 1) s += __shfl_xor_sync(0xffffffffu, s, o);
    float inv = 1.0f / s;
#pragma unroll
    for (int l = 0; l < 5; l++) {
        int idx = lane + 32 * l;
        if (idx < KU) p[idx] = v[l] * inv;
    }
}

// ---------------------------------------------------------------------------
// K5: fused proto GEMM + squared-distance reduction.
// per class c: proto = attn[14000,140] @ class_v[140,1152];
// dist[c,q] += sum_t sum_d (qv - proto)^2, accumulated via atomics.
// ---------------------------------------------------------------------------
__global__ void __launch_bounds__(256)
proto_dist_kernel()
{
    __shared__ float As[8][128];
    __shared__ float Bs[8][128];
    __shared__ float rowsum[128];

    const int M = QROWS, N = DOUT, Kd = KU;
    int c = blockIdx.z;
    const float* A = g_S + c * KU;                    // lda = SROWS (700)
    const float* B = g_sv + (size_t)c * KU * DOUT;    // ldb = DOUT

    int tid = threadIdx.x;
    int tx  = tid & 15;
    int ty  = tid >> 4;
    int mBase = blockIdx.y * 128;
    int nBase = blockIdx.x * 128;

    float acc[8][8];
#pragma unroll
    for (int i = 0; i < 8; i++)
#pragma unroll
        for (int j = 0; j < 8; j++) acc[i][j] = 0.0f;

    int aRow = tid >> 1;
    int aK   = (tid & 1) * 4;

    for (int k0 = 0; k0 < Kd; k0 += 8) {
        {
            int gr = mBase + aRow;
            int kk = k0 + aK;
            if (gr < M && kk < Kd) {
                float4 v = *(const float4*)(A + (size_t)gr * SROWS + kk);
                As[aK + 0][aRow] = v.x; As[aK + 1][aRow] = v.y;
                As[aK + 2][aRow] = v.z; As[aK + 3][aRow] = v.w;
            } else {
                As[aK + 0][aRow] = 0.f; As[aK + 1][aRow] = 0.f;
                As[aK + 2][aRow] = 0.f; As[aK + 3][aRow] = 0.f;
            }
        }
        {
            int bK = tid >> 5;
            int bC = (tid & 31) * 4;
            int kk = k0 + bK;
            if (kk < Kd) {
                float4 v = *(const float4*)(B + (size_t)kk * DOUT + nBase + bC);
                Bs[bK][bC + 0] = v.x; Bs[bK][bC + 1] = v.y;
                Bs[bK][bC + 2] = v.z; Bs[bK][bC + 3] = v.w;
            } else {
                Bs[bK][bC + 0] = 0.f; Bs[bK][bC + 1] = 0.f;
                Bs[bK][bC + 2] = 0.f; Bs[bK][bC + 3] = 0.f;
            }
        }
        __syncthreads();
#pragma unroll
        for (int k = 0; k < 8; k++) {
            float ar[8], br[8];
            *(float4*)&ar[0] = *(const float4*)&As[k][ty * 8];
            *(float4*)&ar[4] = *(const float4*)&As[k][ty * 8 + 4];
            *(float4*)&br[0] = *(const float4*)&Bs[k][tx * 8];
            *(float4*)&br[4] = *(const float4*)&Bs[k][tx * 8 + 4];
#pragma unroll
            for (int i = 0; i < 8; i++)
#pragma unroll
                for (int j = 0; j < 8; j++)
                    acc[i][j] += ar[i] * br[j];
        }
        __syncthreads();
    }

    // epilogue: (qv - proto)^2 row reduction
    if (tid < 128) rowsum[tid] = 0.f;
    __syncthreads();
#pragma unroll
    for (int i = 0; i < 8; i++) {
        int gr = mBase + ty * 8 + i;
        if (gr >= M) continue;
        const float* qrow = g_qv + (size_t)gr * DOUT + nBase + tx * 8;
        float4 q0 = *(const float4*)(qrow);
        float4 q1 = *(const float4*)(qrow + 4);
        float qv8[8] = {q0.x, q0.y, q0.z, q0.w, q1.x, q1.y, q1.z, q1.w};
        float p = 0.f;
#pragma unroll
        for (int j = 0; j < 8; j++) {
            float d = qv8[j] - acc[i][j];
            p += d * d;
        }
        atomicAdd(&rowsum[ty * 8 + i], p);
    }
    __syncthreads();
    if (tid < 128) {
        int gr = mBase + tid;
        if (gr < M) {
            int q = gr / T_LEN;
            atomicAdd(&g_dist[c * NQ + q], rowsum[tid]);
        }
    }
}

// ---------------------------------------------------------------------------
// K6: logits[q, c] = -(dist / 28) * global_temperature * temperature_weight
// ---------------------------------------------------------------------------
__global__ void final_kernel(const float* __restrict__ gt,
                             const float* __restrict__ tw,
                             float* __restrict__ out)
{
    int idx = blockIdx.x * blockDim.x + threadIdx.x;
    if (idx >= NQ * WAY) return;
    int q = idx / WAY;
    int c = idx - q * WAY;
    out[idx] = -(g_dist[c * NQ + q] * (1.0f / T_LEN)) * gt[0] * tw[0];
}

// ---------------------------------------------------------------------------
// launcher
// ---------------------------------------------------------------------------
extern "C" void kernel_launch(void* const* d_in, const int* in_sizes, int n_in,
                              void* d_out, int out_size)
{
    const float* sup   = (const float*)d_in[0];
    // d_in[1] = support_labels (sorted & balanced -> unused, same as reference)
    const float* qry   = (const float*)d_in[2];
    const float* kw    = (const float*)d_in[3];
    const float* kb    = (const float*)d_in[4];
    const float* vw    = (const float*)d_in[5];
    const float* vb    = (const float*)d_in[6];
    const float* gamma = (const float*)d_in[7];
    const float* beta  = (const float*)d_in[8];
    const float* gt    = (const float*)d_in[9];
    const float* tw    = (const float*)d_in[10];
    float* out = (float*)d_out;

    float *pX, *pW, *pP, *pSK, *pQK, *pS;
    cudaGetSymbolAddress((void**)&pX, g_X);
    cudaGetSymbolAddress((void**)&pW, g_W);
    cudaGetSymbolAddress((void**)&pP, g_P);
    cudaGetSymbolAddress((void**)&pSK, g_sk);
    cudaGetSymbolAddress((void**)&pQK, g_qk);
    cudaGetSymbolAddress((void**)&pS, g_S);

    pack_x_kernel<<<(N_FRAMES * FEAT + 255) / 256, 256>>>(sup, qry);
    pack_w_kernel<<<(FEAT * WCOLS + 255) / 256, 256>>>(kw, vw);
    zero_dist_kernel<<<(WAY * NQ + 255) / 256, 256>>>();

    // frame partials: [4200,2048] @ [2048,4608]
    gemm_tile<0><<<dim3(WCOLS / 128, (N_FRAMES + 127) / 128), 256>>>(
        pX, pW, pP, N_FRAMES, WCOLS, FEAT, FEAT, WCOLS, WCOLS, 1.0f);

    combine_ln_kernel<<<N_CLIPS * T_LEN, 256>>>(kb, vb, gamma, beta);

    // scores: [14000,1152] @ [700,1152]^T, scaled by 1/sqrt(1152)
    gemm_tile<1><<<dim3((SROWS + 127) / 128, (QROWS + 127) / 128), 256>>>(
        pQK, pSK, pS, QROWS, SROWS, DOUT, DOUT, DOUT, SROWS,
        0.029462782549439484f);

    softmax_kernel<<<(QROWS * WAY * 32 + 255) / 256, 256>>>();

    proto_dist_kernel<<<dim3(DOUT / 128, (QROWS + 127) / 128, WAY), 256>>>();

    final_kernel<<<(NQ * WAY + 255) / 256, 256>>>(gt, tw, out);
}

// round 9
// speedup vs baseline: 3.1686x; 3.1686x over previous
#include <cuda_runtime.h>
#include <math.h>
#include <stdint.h>

// ---------------------------------------------------------------------------
// Problem constants
// ---------------------------------------------------------------------------
#define SEQ_LEN   8
#define FEAT      2048
#define DOUT      1152
#define WAY       5
#define SHOT      5
#define NQ        500
#define T_LEN     28
#define N_SUP     (WAY * SHOT)           // 25
#define N_CLIPS   (N_SUP + NQ)           // 525
#define N_FRAMES  (N_CLIPS * SEQ_LEN)    // 4200
#define WCOLS     (4 * DOUT)             // 4608 = [k_top | k_bot | v_top | v_bot]
#define SROWS     (N_SUP * T_LEN)        // 700
#define QROWS     (NQ * T_LEN)           // 14000
#define KU        (SHOT * T_LEN)         // 140
#define LN_EPS    1e-5f

// mma.sync tile config
#define BM 128
#define BN 128
#define BK 32
#define PAD 36                                   // smem row stride (floats)
#define STG_FLOATS (2 * BM * PAD)                // A+B per stage = 9216 floats
#define SM_TOTAL (2 * STG_FLOATS * 4)            // 2 stages -> 73728 bytes

__constant__ int2 c_tup[T_LEN] = {
    {0,1},{0,2},{0,3},{0,4},{0,5},{0,6},{0,7},
    {1,2},{1,3},{1,4},{1,5},{1,6},{1,7},
    {2,3},{2,4},{2,5},{2,6},{2,7},
    {3,4},{3,5},{3,6},{3,7},
    {4,5},{4,6},{4,7},
    {5,6},{5,7},
    {6,7}
};

// ---------------------------------------------------------------------------
// Device scratch (allocation-free per harness rules)
// ---------------------------------------------------------------------------
__device__ float g_X[N_FRAMES * FEAT];             // frames + PE (tf32-rounded)
__device__ float g_WT[WCOLS * FEAT];               // packed weights, [4608,2048] K-major
__device__ float g_P[N_FRAMES * WCOLS];            // frame partials (fp32)
__device__ float g_sk[SROWS * DOUT];               // support K (LN'd, tf32)
__device__ float g_svT[WAY * DOUT * KU];           // support V transposed [c][d][ku] (tf32)
__device__ float g_qk[QROWS * DOUT];               // query K (LN'd, tf32)
__device__ float g_qv[QROWS * DOUT];               // query V (fp32)
__device__ float g_S[QROWS * SROWS];               // scores / attn
__device__ float g_dist[WAY * NQ];

// ---------------------------------------------------------------------------
// PTX helpers (baseline ISA only -- no tcgen05: harness targets compute_103)
// ---------------------------------------------------------------------------
__device__ __forceinline__ float to_tf32(float x) {
    float r;
    asm("cvt.rn.tf32.f32 %0, %1;" : "=f"(r) : "f"(x));
    return r;
}

__device__ __forceinline__ uint32_t smem_u32(const void* p) {
    uint32_t a;
    asm("{ .reg .u64 t; cvta.to.shared.u64 t, %1; cvt.u32.u64 %0, t; }" : "=r"(a) : "l"(p));
    return a;
}

__device__ __forceinline__ void cp_async16(uint32_t dst, const void* src, int sz) {
    asm volatile("cp.async.ca.shared.global [%0], [%1], 16, %2;"
                 :: "r"(dst), "l"(src), "r"(sz) : "memory");
}
__device__ __forceinline__ void cp_commit() {
    asm volatile("cp.async.commit_group;" ::: "memory");
}
template<int N>
__device__ __forceinline__ void cp_wait() {
    asm volatile("cp.async.wait_group %0;" :: "n"(N) : "memory");
}

// D += A@B for one m16n8k8 tf32 tile
__device__ __forceinline__ void mma_tf32(float* c, const uint32_t* a, const uint32_t* b) {
    asm volatile(
        "mma.sync.aligned.m16n8k8.row.col.f32.tf32.tf32.f32 "
        "{%0,%1,%2,%3}, {%4,%5,%6,%7}, {%8,%9}, {%0,%1,%2,%3};"
        : "+f"(c[0]), "+f"(c[1]), "+f"(c[2]), "+f"(c[3])
        : "r"(a[0]), "r"(a[1]), "r"(a[2]), "r"(a[3]), "r"(b[0]), "r"(b[1]));
}

// ---------------------------------------------------------------------------
// K0a: X = frames + positional encoding (tf32-rounded)
// ---------------------------------------------------------------------------
__global__ void pack_x_kernel(const float* __restrict__ sup,
                              const float* __restrict__ qry)
{
    int idx = blockIdx.x * blockDim.x + threadIdx.x;
    if (idx >= N_FRAMES * FEAT) return;
    int d   = idx & (FEAT - 1);
    int row = idx >> 11;
    int f   = row & 7;

    const float c = -9.210340371976184f / 2048.0f;
    int  i2  = d >> 1;
    float dv = expf((float)(2 * i2) * c);
    float arg = (float)f * dv;
    float pe  = (d & 1) ? cosf(arg) : sinf(arg);

    float x = (row < N_SUP * SEQ_LEN) ? sup[idx] : qry[idx - N_SUP * SEQ_LEN * FEAT];
    g_X[idx] = to_tf32(x + pe);
}

// ---------------------------------------------------------------------------
// K0b: WT[n,k] = W_packed[k,n], tiled transpose, tf32-rounded.
// ---------------------------------------------------------------------------
__global__ void pack_wt_kernel(const float* __restrict__ kw,
                               const float* __restrict__ vw)
{
    __shared__ float t[32][33];
    int n0 = blockIdx.x * 32;
    int k0 = blockIdx.y * 32;
    int tx = threadIdx.x, ty = threadIdx.y;   // 32x8

    int blk = n0 / DOUT;                 // constant per tile (1152 % 32 == 0)
    const float* src = (blk < 2) ? kw : vw;
    int half = blk & 1;
    int jj0  = n0 - blk * DOUT;

#pragma unroll
    for (int i = 0; i < 4; i++) {
        int k = k0 + ty + i * 8;
        t[ty + i * 8][tx] = src[(size_t)(half * FEAT + k) * DOUT + jj0 + tx];
    }
    __syncthreads();
#pragma unroll
    for (int i = 0; i < 4; i++) {
        int n = n0 + ty + i * 8;
        g_WT[(size_t)n * FEAT + k0 + tx] = to_tf32(t[tx][ty + i * 8]);
    }
}

__global__ void zero_dist_kernel()
{
    int idx = blockIdx.x * blockDim.x + threadIdx.x;
    if (idx < WAY * NQ) g_dist[idx] = 0.0f;
}

// ---------------------------------------------------------------------------
// tf32 mma.sync GEMM: C[M,N] = A[M,K] @ B[N,K]^T (both K-major).
// 128x128x32 block tile, 8 warps (4M x 2N), warp tile 32x64, 2-stage cp.async.
// MODE 0: store C.  MODE 1: store C*scale w/ col guard (scores).
// MODE 2: fused (qv - C)^2 row-reduction -> atomicAdd g_dist; blockIdx.z=class.
// ---------------------------------------------------------------------------
template<int MODE>
__global__ void __launch_bounds__(256)
mma_gemm(const float* __restrict__ Ain, const float* __restrict__ Bin,
         float* __restrict__ C, int M, int N, int K,
         int lda, int ldb, int ldc, float scale)
{
    extern __shared__ float sm[];
    int tid  = threadIdx.x;
    int wid  = tid >> 5, lane = tid & 31;
    int gid  = lane >> 2, tig = lane & 3;
    int wy   = wid & 3,  wx  = wid >> 2;
    int mBase = blockIdx.y * BM;
    int nBase = blockIdx.x * BN;

    const float* A = Ain;
    const float* B = Bin;
    int cls = 0;
    if (MODE == 2) {
        cls = blockIdx.z;
        A += cls * KU;                        // g_S + c*140, lda = 700
        B += (size_t)cls * DOUT * KU;         // g_svT class block, ldb = 140
    }

    float acc[2][8][4];
#pragma unroll
    for (int i = 0; i < 2; i++)
#pragma unroll
        for (int j = 0; j < 8; j++)
#pragma unroll
            for (int l = 0; l < 4; l++) acc[i][j][l] = 0.f;

    const int nIter = (K + BK - 1) / BK;
    uint32_t sbase = smem_u32(sm);

    // stage loader: A tile [128 x 32] + B tile [128 x 32], float4 cp.async
    auto load_stage = [&](int it, int s) {
        int k0 = it * BK;
        uint32_t stg = sbase + (uint32_t)s * (STG_FLOATS * 4);
#pragma unroll
        for (int p = 0; p < 4; p++) {
            int i = tid + p * 256;
            int r = i >> 3, seg = i & 7;
            int gr = mBase + r, gk = k0 + seg * 4;
            int ok = (gr < M) & (gk < K);
            const float* src = ok ? (A + (size_t)gr * lda + gk) : A;
            cp_async16(stg + (uint32_t)(r * PAD + seg * 4) * 4, src, ok ? 16 : 0);
        }
#pragma unroll
        for (int p = 0; p < 4; p++) {
            int i = tid + p * 256;
            int r = i >> 3, seg = i & 7;
            int gn = nBase + r, gk = k0 + seg * 4;
            int ok = (gn < N) & (gk < K);
            const float* src = ok ? (B + (size_t)gn * ldb + gk) : B;
            cp_async16(stg + (uint32_t)(BM * PAD + r * PAD + seg * 4) * 4, src, ok ? 16 : 0);
        }
        cp_commit();
    };

    load_stage(0, 0);

    for (int it = 0; it < nIter; it++) {
        bool more = (it + 1 < nIter);
        if (more) load_stage(it + 1, (it + 1) & 1);
        if (more) cp_wait<1>(); else cp_wait<0>();
        __syncthreads();

        const float* As = sm + (it & 1) * STG_FLOATS;
        const float* Bs = As + BM * PAD;

#pragma unroll
        for (int kk = 0; kk < BK; kk += 8) {
            uint32_t af[2][4];
            uint32_t bf[8][2];
#pragma unroll
            for (int mt = 0; mt < 2; mt++) {
                const float* pa = As + (wy * 32 + mt * 16 + gid) * PAD + kk + tig;
                af[mt][0] = __float_as_uint(pa[0]);
                af[mt][1] = __float_as_uint(pa[8 * PAD]);
                af[mt][2] = __float_as_uint(pa[4]);
                af[mt][3] = __float_as_uint(pa[8 * PAD + 4]);
            }
#pragma unroll
            for (int nt = 0; nt < 8; nt++) {
                const float* pb = Bs + (wx * 64 + nt * 8 + gid) * PAD + kk + tig;
                bf[nt][0] = __float_as_uint(pb[0]);
                bf[nt][1] = __float_as_uint(pb[4]);
            }
#pragma unroll
            for (int mt = 0; mt < 2; mt++)
#pragma unroll
                for (int nt = 0; nt < 8; nt++)
                    mma_tf32(acc[mt][nt], af[mt], bf[nt]);
        }
        __syncthreads();
    }

    // ------------------------------------------------------------ epilogue
    if (MODE == 2) {
        // fused (qv - proto)^2 -> per-row sums -> g_dist
        float* rowsum = sm;                       // reuse smem (post-sync)
        if (tid < BM) rowsum[tid] = 0.f;
        __syncthreads();
#pragma unroll
        for (int mt = 0; mt < 2; mt++) {
#pragma unroll
            for (int h = 0; h < 2; h++) {
                int rloc = wy * 32 + mt * 16 + gid + 8 * h;
                int gr = mBase + rloc;
                if (gr < M) {
                    float s = 0.f;
#pragma unroll
                    for (int nt = 0; nt < 8; nt++) {
                        int gc = nBase + wx * 64 + nt * 8 + tig * 2;
                        float2 q = *(const float2*)(g_qv + (size_t)gr * DOUT + gc);
                        float d0 = q.x - acc[mt][nt][2 * h];
                        float d1 = q.y - acc[mt][nt][2 * h + 1];
                        s += d0 * d0 + d1 * d1;
                    }
                    atomicAdd(&rowsum[rloc], s);
                }
            }
        }
        __syncthreads();
        if (tid < BM) {
            int gr = mBase + tid;
            if (gr < M) atomicAdd(&g_dist[cls * NQ + gr / T_LEN], rowsum[tid]);
        }
    } else {
#pragma unroll
        for (int mt = 0; mt < 2; mt++) {
#pragma unroll
            for (int h = 0; h < 2; h++) {
                int gr = mBase + wy * 32 + mt * 16 + gid + 8 * h;
                if (gr >= M) continue;
                float* crow = C + (size_t)gr * ldc;
#pragma unroll
                for (int nt = 0; nt < 8; nt++) {
                    int gc = nBase + wx * 64 + nt * 8 + tig * 2;
                    if (MODE == 1 && gc >= N) continue;  // N even, pair-safe
                    float2 v;
                    v.x = acc[mt][nt][2 * h] * scale;
                    v.y = acc[mt][nt][2 * h + 1] * scale;
                    *(float2*)(crow + gc) = v;
                }
            }
        }
    }
}

// ---------------------------------------------------------------------------
// K2: combine frame partials + bias; LN on K path.
// ---------------------------------------------------------------------------
__global__ void __launch_bounds__(256)
combine_ln_kernel(const float* __restrict__ kb, const float* __restrict__ vb,
                  const float* __restrict__ gamma, const float* __restrict__ beta)
{
    __shared__ float buf[DOUT];
    __shared__ float rs[8], rq[8];

    int r = blockIdx.x;
    int n = r / T_LEN;
    int t = r - n * T_LEN;
    int2 tp = c_tup[t];

    const float* pi = g_P + (size_t)(n * SEQ_LEN + tp.x) * WCOLS;
    const float* pj = g_P + (size_t)(n * SEQ_LEN + tp.y) * WCOLS;

    float* kout;
    float* qvout = nullptr;
    float* svTout = nullptr;
    if (n < N_SUP) {
        kout = g_sk + (size_t)r * DOUT;
        int c  = n / SHOT;
        int ku = (n - c * SHOT) * T_LEN + t;
        svTout = g_svT + (size_t)c * DOUT * KU + ku;    // + d*KU per element
    } else {
        size_t qr = (size_t)(r - SROWS) * DOUT;
        kout  = g_qk + qr;
        qvout = g_qv + qr;
    }

    int tid = threadIdx.x;
    float s = 0.f, sq = 0.f;
    for (int d = tid; d < DOUT; d += 256) {
        float kv = pi[d] + pj[DOUT + d] + kb[d];
        buf[d] = kv;
        s += kv; sq += kv * kv;
        float vv = pi[2 * DOUT + d] + pj[3 * DOUT + d] + vb[d];
        if (qvout) qvout[d] = vv;
        else       svTout[(size_t)d * KU] = to_tf32(vv);
    }
#pragma unroll
    for (int o = 16; o; o >>= 1) {
        s  += __shfl_xor_sync(0xffffffffu, s, o);
        sq += __shfl_xor_sync(0xffffffffu, sq, o);
    }
    int lane = tid & 31, wid = tid >> 5;
    if (lane == 0) { rs[wid] = s; rq[wid] = sq; }
    __syncthreads();
    if (tid == 0) {
        float S = 0.f, Q = 0.f;
#pragma unroll
        for (int w = 0; w < 8; w++) { S += rs[w]; Q += rq[w]; }
        rs[0] = S; rq[0] = Q;
    }
    __syncthreads();
    float mean = rs[0] * (1.0f / DOUT);
    float var  = rq[0] * (1.0f / DOUT) - mean * mean;
    float rstd = rsqrtf(var + LN_EPS);
    for (int d = tid; d < DOUT; d += 256)
        kout[d] = to_tf32((buf[d] - mean) * rstd * gamma[d] + beta[d]);
}

// ---------------------------------------------------------------------------
// K4: softmax over 140-chunks (attn tf32-rounded for the proto MMA)
// ---------------------------------------------------------------------------
__global__ void softmax_kernel()
{
    int warp = (blockIdx.x * blockDim.x + threadIdx.x) >> 5;
    if (warp >= QROWS * WAY) return;
    int lane = threadIdx.x & 31;
    int row = warp / WAY;
    int c   = warp - row * WAY;
    float* p = g_S + (size_t)row * SROWS + c * KU;

    float v[5];
    float mx = -1e30f;
#pragma unroll
    for (int l = 0; l < 5; l++) {
        int idx = lane + 32 * l;
        v[l] = (idx < KU) ? p[idx] : -1e30f;
        mx = fmaxf(mx, v[l]);
    }
#pragma unroll
    for (int o = 16; o; o >>= 1) mx = fmaxf(mx, __shfl_xor_sync(0xffffffffu, mx, o));
    float s = 0.f;
#pragma unroll
    for (int l = 0; l < 5; l++) {
        int idx = lane + 32 * l;
        v[l] = (idx < KU) ? expf(v[l] - mx) : 0.f;
        s += v[l];
    }
#pragma unroll
    for (int o = 16; o; o >>= 1) s += __shfl_xor_sync(0xffffffffu, s, o);
    float inv = 1.0f / s;
#pragma unroll
    for (int l = 0; l < 5; l++) {
        int idx = lane + 32 * l;
        if (idx < KU) p[idx] = to_tf32(v[l] * inv);
    }
}

// ---------------------------------------------------------------------------
// K6: logits[q, c]
// ---------------------------------------------------------------------------
__global__ void final_kernel(const float* __restrict__ gt,
                             const float* __restrict__ tw,
                             float* __restrict__ out)
{
    int idx = blockIdx.x * blockDim.x + threadIdx.x;
    if (idx >= NQ * WAY) return;
    int q = idx / WAY;
    int c = idx - q * WAY;
    out[idx] = -(g_dist[c * NQ + q] * (1.0f / T_LEN)) * gt[0] * tw[0];
}

// ---------------------------------------------------------------------------
// launcher
// ---------------------------------------------------------------------------
extern "C" void kernel_launch(void* const* d_in, const int* in_sizes, int n_in,
                              void* d_out, int out_size)
{
    const float* sup   = (const float*)d_in[0];
    // d_in[1] = support_labels (sorted & balanced -> implicit reshape)
    const float* qry   = (const float*)d_in[2];
    const float* kw    = (const float*)d_in[3];
    const float* kb    = (const float*)d_in[4];
    const float* vw    = (const float*)d_in[5];
    const float* vb    = (const float*)d_in[6];
    const float* gamma = (const float*)d_in[7];
    const float* beta  = (const float*)d_in[8];
    const float* gt    = (const float*)d_in[9];
    const float* tw    = (const float*)d_in[10];
    float* out = (float*)d_out;

    float *pX, *pWT, *pP, *pSK, *pSVT, *pQK, *pS;
    cudaGetSymbolAddress((void**)&pX,  g_X);
    cudaGetSymbolAddress((void**)&pWT, g_WT);
    cudaGetSymbolAddress((void**)&pP,  g_P);
    cudaGetSymbolAddress((void**)&pSK, g_sk);
    cudaGetSymbolAddress((void**)&pSVT, g_svT);
    cudaGetSymbolAddress((void**)&pQK, g_qk);
    cudaGetSymbolAddress((void**)&pS,  g_S);

    static bool attr_done = false;
    if (!attr_done) {
        cudaFuncSetAttribute(mma_gemm<0>, cudaFuncAttributeMaxDynamicSharedMemorySize, SM_TOTAL);
        cudaFuncSetAttribute(mma_gemm<1>, cudaFuncAttributeMaxDynamicSharedMemorySize, SM_TOTAL);
        cudaFuncSetAttribute(mma_gemm<2>, cudaFuncAttributeMaxDynamicSharedMemorySize, SM_TOTAL);
        attr_done = true;
    }

    pack_x_kernel<<<(N_FRAMES * FEAT + 255) / 256, 256>>>(sup, qry);
    pack_wt_kernel<<<dim3(WCOLS / 32, FEAT / 32), dim3(32, 8)>>>(kw, vw);
    zero_dist_kernel<<<(WAY * NQ + 255) / 256, 256>>>();

    // frame partials: [4200,2048] @ [4608,2048]^T
    mma_gemm<0><<<dim3(WCOLS / BN, (N_FRAMES + BM - 1) / BM), 256, SM_TOTAL>>>(
        pX, pWT, pP, N_FRAMES, WCOLS, FEAT, FEAT, FEAT, WCOLS, 1.0f);

    combine_ln_kernel<<<N_CLIPS * T_LEN, 256>>>(kb, vb, gamma, beta);

    // scores: [14000,1152] @ [700,1152]^T, scaled by 1/sqrt(1152)
    mma_gemm<1><<<dim3((SROWS + BN - 1) / BN, (QROWS + BM - 1) / BM), 256, SM_TOTAL>>>(
        pQK, pSK, pS, QROWS, SROWS, DOUT, DOUT, DOUT, SROWS,
        0.029462782549439484f);

    softmax_kernel<<<(QROWS * WAY * 32 + 255) / 256, 256>>>();

    // proto + fused distance: per class, attn[14000,140] @ svT[1152,140]^T
    mma_gemm<2><<<dim3((DOUT + BN - 1) / BN, (QROWS + BM - 1) / BM, WAY), 256, SM_TOTAL>>>(
        pS, pSVT, nullptr, QROWS, DOUT, KU, SROWS, KU, 0, 1.0f);

    final_kernel<<<(NQ * WAY + 255) / 256, 256>>>(gt, tw, out);
}

// round 11
// speedup vs baseline: 3.4282x; 1.0819x over previous
#include <cuda_runtime.h>
#include <math.h>
#include <stdint.h>

// ---------------------------------------------------------------------------
// Problem constants
// ---------------------------------------------------------------------------
#define SEQ_LEN   8
#define FEAT      2048
#define DOUT      1152
#define WAY       5
#define SHOT      5
#define NQ        500
#define T_LEN     28
#define N_SUP     (WAY * SHOT)           // 25
#define N_CLIPS   (N_SUP + NQ)           // 525
#define N_FRAMES  (N_CLIPS * SEQ_LEN)    // 4200
#define WCOLS     (4 * DOUT)             // 4608 = [k_top | k_bot | v_top | v_bot]
#define SROWS     (N_SUP * T_LEN)        // 700
#define QROWS     (NQ * T_LEN)           // 14000
#define KU        (SHOT * T_LEN)         // 140
#define LN_EPS    1e-5f

// mma.sync tile config
#define BM 128
#define BN 128
#define BK 32
#define PAD 36                                   // smem row stride (floats)
#define STG_FLOATS (2 * BM * PAD)                // A+B per stage = 9216 floats
#define SM_TOTAL (2 * STG_FLOATS * 4)            // 2 stages -> 73728 bytes

__constant__ int2 c_tup[T_LEN] = {
    {0,1},{0,2},{0,3},{0,4},{0,5},{0,6},{0,7},
    {1,2},{1,3},{1,4},{1,5},{1,6},{1,7},
    {2,3},{2,4},{2,5},{2,6},{2,7},
    {3,4},{3,5},{3,6},{3,7},
    {4,5},{4,6},{4,7},
    {5,6},{5,7},
    {6,7}
};

// ---------------------------------------------------------------------------
// Device scratch (allocation-free per harness rules)
// ---------------------------------------------------------------------------
__device__ float g_PE[SEQ_LEN * FEAT];             // positional-encoding table
__device__ float g_X[N_FRAMES * FEAT];             // frames + PE (tf32-rounded)
__device__ float g_WT[WCOLS * FEAT];               // packed weights, [4608,2048] K-major
__device__ float g_P[N_FRAMES * WCOLS];            // frame partials (fp32)
__device__ float g_sk[SROWS * DOUT];               // support K (LN'd, tf32)
__device__ float g_svT[WAY * DOUT * KU];           // support V transposed [c][d][ku] (tf32)
__device__ float g_qk[QROWS * DOUT];               // query K (LN'd, tf32)
__device__ float g_qv[QROWS * DOUT];               // query V (fp32)
__device__ float g_S[QROWS * SROWS];               // scores / attn
__device__ float g_dist[WAY * NQ];

// ---------------------------------------------------------------------------
// PTX helpers (baseline ISA only -- no tcgen05: harness targets compute_103)
// ---------------------------------------------------------------------------
__device__ __forceinline__ float to_tf32(float x) {
    float r;
    asm("cvt.rn.tf32.f32 %0, %1;" : "=f"(r) : "f"(x));
    return r;
}

__device__ __forceinline__ uint32_t smem_u32(const void* p) {
    uint32_t a;
    asm("{ .reg .u64 t; cvta.to.shared.u64 t, %1; cvt.u32.u64 %0, t; }" : "=r"(a) : "l"(p));
    return a;
}

// .cg = bypass L1 (L2 only) -- keeps the L1/shared path clear for LDS traffic
__device__ __forceinline__ void cp_async16(uint32_t dst, const void* src, int sz) {
    asm volatile("cp.async.cg.shared.global [%0], [%1], 16, %2;"
                 :: "r"(dst), "l"(src), "r"(sz) : "memory");
}
__device__ __forceinline__ void cp_commit() {
    asm volatile("cp.async.commit_group;" ::: "memory");
}
template<int N>
__device__ __forceinline__ void cp_wait() {
    asm volatile("cp.async.wait_group %0;" :: "n"(N) : "memory");
}

// D += A@B for one m16n8k8 tf32 tile
__device__ __forceinline__ void mma_tf32(float* c, const uint32_t* a, const uint32_t* b) {
    asm volatile(
        "mma.sync.aligned.m16n8k8.row.col.f32.tf32.tf32.f32 "
        "{%0,%1,%2,%3}, {%4,%5,%6,%7}, {%8,%9}, {%0,%1,%2,%3};"
        : "+f"(c[0]), "+f"(c[1]), "+f"(c[2]), "+f"(c[3])
        : "r"(a[0]), "r"(a[1]), "r"(a[2]), "r"(a[3]), "r"(b[0]), "r"(b[1]));
}

// ---------------------------------------------------------------------------
// K0pe: positional-encoding table [8, 2048] (one-time transcendentals)
// ---------------------------------------------------------------------------
__global__ void pe_kernel()
{
    int idx = blockIdx.x * blockDim.x + threadIdx.x;
    if (idx >= SEQ_LEN * FEAT) return;
    int d = idx & (FEAT - 1);
    int f = idx >> 11;
    const float c = -9.210340371976184f / 2048.0f;
    int  i2  = d >> 1;
    float dv = expf((float)(2 * i2) * c);
    float arg = (float)f * dv;
    g_PE[idx] = (d & 1) ? cosf(arg) : sinf(arg);
}

// ---------------------------------------------------------------------------
// K0a: X = frames + PE (tf32-rounded), pure streaming
// ---------------------------------------------------------------------------
__global__ void pack_x_kernel(const float* __restrict__ sup,
                              const float* __restrict__ qry)
{
    int idx = blockIdx.x * blockDim.x + threadIdx.x;
    if (idx >= N_FRAMES * FEAT) return;
    int d   = idx & (FEAT - 1);
    int row = idx >> 11;
    int f   = row & 7;
    float pe = g_PE[f * FEAT + d];
    float x = (row < N_SUP * SEQ_LEN) ? sup[idx] : qry[idx - N_SUP * SEQ_LEN * FEAT];
    g_X[idx] = to_tf32(x + pe);
}

// ---------------------------------------------------------------------------
// K0b: WT[n,k] = W_packed[k,n], tiled transpose, tf32-rounded.
// ---------------------------------------------------------------------------
__global__ void pack_wt_kernel(const float* __restrict__ kw,
                               const float* __restrict__ vw)
{
    __shared__ float t[32][33];
    int n0 = blockIdx.x * 32;
    int k0 = blockIdx.y * 32;
    int tx = threadIdx.x, ty = threadIdx.y;   // 32x8

    int blk = n0 / DOUT;                 // constant per tile (1152 % 32 == 0)
    const float* src = (blk < 2) ? kw : vw;
    int half = blk & 1;
    int jj0  = n0 - blk * DOUT;

#pragma unroll
    for (int i = 0; i < 4; i++) {
        int k = k0 + ty + i * 8;
        t[ty + i * 8][tx] = src[(size_t)(half * FEAT + k) * DOUT + jj0 + tx];
    }
    __syncthreads();
#pragma unroll
    for (int i = 0; i < 4; i++) {
        int n = n0 + ty + i * 8;
        g_WT[(size_t)n * FEAT + k0 + tx] = to_tf32(t[tx][ty + i * 8]);
    }
}

__global__ void zero_dist_kernel()
{
    int idx = blockIdx.x * blockDim.x + threadIdx.x;
    if (idx < WAY * NQ) g_dist[idx] = 0.0f;
}

// ---------------------------------------------------------------------------
// tf32 mma.sync GEMM: C[M,N] = A[M,K] @ B[N,K]^T (both K-major).
// 128x128x32 block tile, 8 warps (4M x 2N), warp tile 32x64, 2-stage cp.async.
// __launch_bounds__(256, 2): cap regs at 128 -> 2 CTAs/SM (occ 12.5% -> 25%).
// MODE 0: store C.  MODE 1: store C*scale w/ col guard (scores).
// MODE 2: fused (qv - C)^2 row-reduction -> atomicAdd g_dist; blockIdx.z=class.
// ---------------------------------------------------------------------------
template<int MODE>
__global__ void __launch_bounds__(256, 2)
mma_gemm(const float* __restrict__ Ain, const float* __restrict__ Bin,
         float* __restrict__ C, int M, int N, int K,
         int lda, int ldb, int ldc, float scale)
{
    extern __shared__ float sm[];
    int tid  = threadIdx.x;
    int wid  = tid >> 5, lane = tid & 31;
    int gid  = lane >> 2, tig = lane & 3;
    int wy   = wid & 3,  wx  = wid >> 2;
    int mBase = blockIdx.y * BM;
    int nBase = blockIdx.x * BN;

    const float* A = Ain;
    const float* B = Bin;
    int cls = 0;
    if (MODE == 2) {
        cls = blockIdx.z;
        A += cls * KU;                        // g_S + c*140, lda = 700
        B += (size_t)cls * DOUT * KU;         // g_svT class block, ldb = 140
    }

    float acc[2][8][4];
#pragma unroll
    for (int i = 0; i < 2; i++)
#pragma unroll
        for (int j = 0; j < 8; j++)
#pragma unroll
            for (int l = 0; l < 4; l++) acc[i][j][l] = 0.f;

    const int nIter = (K + BK - 1) / BK;
    uint32_t sbase = smem_u32(sm);

    // stage loader: A tile [128 x 32] + B tile [128 x 32], float4 cp.async
    auto load_stage = [&](int it, int s) {
        int k0 = it * BK;
        uint32_t stg = sbase + (uint32_t)s * (STG_FLOATS * 4);
#pragma unroll
        for (int p = 0; p < 4; p++) {
            int i = tid + p * 256;
            int r = i >> 3, seg = i & 7;
            int gr = mBase + r, gk = k0 + seg * 4;
            int ok = (gr < M) & (gk < K);
            const float* src = ok ? (A + (size_t)gr * lda + gk) : A;
            cp_async16(stg + (uint32_t)(r * PAD + seg * 4) * 4, src, ok ? 16 : 0);
        }
#pragma unroll
        for (int p = 0; p < 4; p++) {
            int i = tid + p * 256;
            int r = i >> 3, seg = i & 7;
            int gn = nBase + r, gk = k0 + seg * 4;
            int ok = (gn < N) & (gk < K);
            const float* src = ok ? (B + (size_t)gn * ldb + gk) : B;
            cp_async16(stg + (uint32_t)(BM * PAD + r * PAD + seg * 4) * 4, src, ok ? 16 : 0);
        }
        cp_commit();
    };

    load_stage(0, 0);

    for (int it = 0; it < nIter; it++) {
        bool more = (it + 1 < nIter);
        if (more) load_stage(it + 1, (it + 1) & 1);
        if (more) cp_wait<1>(); else cp_wait<0>();
        __syncthreads();

        const float* As = sm + (it & 1) * STG_FLOATS;
        const float* Bs = As + BM * PAD;

#pragma unroll
        for (int kk = 0; kk < BK; kk += 8) {
            uint32_t af[2][4];
            uint32_t bf[8][2];
#pragma unroll
            for (int mt = 0; mt < 2; mt++) {
                const float* pa = As + (wy * 32 + mt * 16 + gid) * PAD + kk + tig;
                af[mt][0] = __float_as_uint(pa[0]);
                af[mt][1] = __float_as_uint(pa[8 * PAD]);
                af[mt][2] = __float_as_uint(pa[4]);
                af[mt][3] = __float_as_uint(pa[8 * PAD + 4]);
            }
#pragma unroll
            for (int nt = 0; nt < 8; nt++) {
                const float* pb = Bs + (wx * 64 + nt * 8 + gid) * PAD + kk + tig;
                bf[nt][0] = __float_as_uint(pb[0]);
                bf[nt][1] = __float_as_uint(pb[4]);
            }
#pragma unroll
            for (int mt = 0; mt < 2; mt++)
#pragma unroll
                for (int nt = 0; nt < 8; nt++)
                    mma_tf32(acc[mt][nt], af[mt], bf[nt]);
        }
        __syncthreads();
    }

    // ------------------------------------------------------------ epilogue
    if (MODE == 2) {
        // fused (qv - proto)^2 -> per-row sums -> g_dist
        float* rowsum = sm;                       // reuse smem (post-sync)
        if (tid < BM) rowsum[tid] = 0.f;
        __syncthreads();
#pragma unroll
        for (int mt = 0; mt < 2; mt++) {
#pragma unroll
            for (int h = 0; h < 2; h++) {
                int rloc = wy * 32 + mt * 16 + gid + 8 * h;
                int gr = mBase + rloc;
                if (gr < M) {
                    float s = 0.f;
#pragma unroll
                    for (int nt = 0; nt < 8; nt++) {
                        int gc = nBase + wx * 64 + nt * 8 + tig * 2;
                        float2 q = *(const float2*)(g_qv + (size_t)gr * DOUT + gc);
                        float d0 = q.x - acc[mt][nt][2 * h];
                        float d1 = q.y - acc[mt][nt][2 * h + 1];
                        s += d0 * d0 + d1 * d1;
                    }
                    atomicAdd(&rowsum[rloc], s);
                }
            }
        }
        __syncthreads();
        if (tid < BM) {
            int gr = mBase + tid;
            if (gr < M) atomicAdd(&g_dist[cls * NQ + gr / T_LEN], rowsum[tid]);
        }
    } else {
#pragma unroll
        for (int mt = 0; mt < 2; mt++) {
#pragma unroll
            for (int h = 0; h < 2; h++) {
                int gr = mBase + wy * 32 + mt * 16 + gid + 8 * h;
                if (gr >= M) continue;
                float* crow = C + (size_t)gr * ldc;
#pragma unroll
                for (int nt = 0; nt < 8; nt++) {
                    int gc = nBase + wx * 64 + nt * 8 + tig * 2;
                    if (MODE == 1 && gc >= N) continue;  // N even, pair-safe
                    float2 v;
                    v.x = acc[mt][nt][2 * h] * scale;
                    v.y = acc[mt][nt][2 * h + 1] * scale;
                    *(float2*)(crow + gc) = v;
                }
            }
        }
    }
}

// ---------------------------------------------------------------------------
// K2: combine frame partials + bias; LN on K path.
// ---------------------------------------------------------------------------
__global__ void __launch_bounds__(256)
combine_ln_kernel(const float* __restrict__ kb, const float* __restrict__ vb,
                  const float* __restrict__ gamma, const float* __restrict__ beta)
{
    __shared__ float buf[DOUT];
    __shared__ float rs[8], rq[8];

    int r = blockIdx.x;
    int n = r / T_LEN;
    int t = r - n * T_LEN;
    int2 tp = c_tup[t];

    const float* pi = g_P + (size_t)(n * SEQ_LEN + tp.x) * WCOLS;
    const float* pj = g_P + (size_t)(n * SEQ_LEN + tp.y) * WCOLS;

    float* kout;
    float* qvout = nullptr;
    float* svTout = nullptr;
    if (n < N_SUP) {
        kout = g_sk + (size_t)r * DOUT;
        int c  = n / SHOT;
        int ku = (n - c * SHOT) * T_LEN + t;
        svTout = g_svT + (size_t)c * DOUT * KU + ku;    // + d*KU per element
    } else {
        size_t qr = (size_t)(r - SROWS) * DOUT;
        kout  = g_qk + qr;
        qvout = g_qv + qr;
    }

    int tid = threadIdx.x;
    float s = 0.f, sq = 0.f;
    for (int d = tid; d < DOUT; d += 256) {
        float kv = pi[d] + pj[DOUT + d] + kb[d];
        buf[d] = kv;
        s += kv; sq += kv * kv;
        float vv = pi[2 * DOUT + d] + pj[3 * DOUT + d] + vb[d];
        if (qvout) qvout[d] = vv;
        else       svTout[(size_t)d * KU] = to_tf32(vv);
    }
#pragma unroll
    for (int o = 16; o; o >>= 1) {
        s  += __shfl_xor_sync(0xffffffffu, s, o);
        sq += __shfl_xor_sync(0xffffffffu, sq, o);
    }
    int lane = tid & 31, wid = tid >> 5;
    if (lane == 0) { rs[wid] = s; rq[wid] = sq; }
    __syncthreads();
    if (tid == 0) {
        float S = 0.f, Q = 0.f;
#pragma unroll
        for (int w = 0; w < 8; w++) { S += rs[w]; Q += rq[w]; }
        rs[0] = S; rq[0] = Q;
    }
    __syncthreads();
    float mean = rs[0] * (1.0f / DOUT);
    float var  = rq[0] * (1.0f / DOUT) - mean * mean;
    float rstd = rsqrtf(var + LN_EPS);
    for (int d = tid; d < DOUT; d += 256)
        kout[d] = to_tf32((buf[d] - mean) * rstd * gamma[d] + beta[d]);
}

// ---------------------------------------------------------------------------
// K4: softmax over 140-chunks (attn tf32-rounded for the proto MMA)
// ---------------------------------------------------------------------------
__global__ void softmax_kernel()
{
    int warp = (blockIdx.x * blockDim.x + threadIdx.x) >> 5;
    if (warp >= QROWS * WAY) return;
    int lane = threadIdx.x & 31;
    int row = warp / WAY;
    int c   = warp - row * WAY;
    float* p = g_S + (size_t)row * SROWS + c * KU;

    float v[5];
    float mx = -1e30f;
#pragma unroll
    for (int l = 0; l < 5; l++) {
        int idx = lane + 32 * l;
        v[l] = (idx < KU) ? p[idx] : -1e30f;
        mx = fmaxf(mx, v[l]);
    }
#pragma unroll
    for (int o = 16; o; o >>= 1) mx = fmaxf(mx, __shfl_xor_sync(0xffffffffu, mx, o));
    float s = 0.f;
#pragma unroll
    for (int l = 0; l < 5; l++) {
        int idx = lane + 32 * l;
        v[l] = (idx < KU) ? expf(v[l] - mx) : 0.f;
        s += v[l];
    }
#pragma unroll
    for (int o = 16; o; o >>= 1) s += __shfl_xor_sync(0xffffffffu, s, o);
    float inv = 1.0f / s;
#pragma unroll
    for (int l = 0; l < 5; l++) {
        int idx = lane + 32 * l;
        if (idx < KU) p[idx] = to_tf32(v[l] * inv);
    }
}

// ---------------------------------------------------------------------------
// K6: logits[q, c]
// ---------------------------------------------------------------------------
__global__ void final_kernel(const float* __restrict__ gt,
                             const float* __restrict__ tw,
                             float* __restrict__ out)
{
    int idx = blockIdx.x * blockDim.x + threadIdx.x;
    if (idx >= NQ * WAY) return;
    int q = idx / WAY;
    int c = idx - q * WAY;
    out[idx] = -(g_dist[c * NQ + q] * (1.0f / T_LEN)) * gt[0] * tw[0];
}

// ---------------------------------------------------------------------------
// launcher
// ---------------------------------------------------------------------------
extern "C" void kernel_launch(void* const* d_in, const int* in_sizes, int n_in,
                              void* d_out, int out_size)
{
    const float* sup   = (const float*)d_in[0];
    // d_in[1] = support_labels (sorted & balanced -> implicit reshape)
    const float* qry   = (const float*)d_in[2];
    const float* kw    = (const float*)d_in[3];
    const float* kb    = (const float*)d_in[4];
    const float* vw    = (const float*)d_in[5];
    const float* vb    = (const float*)d_in[6];
    const float* gamma = (const float*)d_in[7];
    const float* beta  = (const float*)d_in[8];
    const float* gt    = (const float*)d_in[9];
    const float* tw    = (const float*)d_in[10];
    float* out = (float*)d_out;

    float *pX, *pWT, *pP, *pSK, *pSVT, *pQK, *pS;
    cudaGetSymbolAddress((void**)&pX,  g_X);
    cudaGetSymbolAddress((void**)&pWT, g_WT);
    cudaGetSymbolAddress((void**)&pP,  g_P);
    cudaGetSymbolAddress((void**)&pSK, g_sk);
    cudaGetSymbolAddress((void**)&pSVT, g_svT);
    cudaGetSymbolAddress((void**)&pQK, g_qk);
    cudaGetSymbolAddress((void**)&pS,  g_S);

    static bool attr_done = false;
    if (!attr_done) {
        cudaFuncSetAttribute(mma_gemm<0>, cudaFuncAttributeMaxDynamicSharedMemorySize, SM_TOTAL);
        cudaFuncSetAttribute(mma_gemm<1>, cudaFuncAttributeMaxDynamicSharedMemorySize, SM_TOTAL);
        cudaFuncSetAttribute(mma_gemm<2>, cudaFuncAttributeMaxDynamicSharedMemorySize, SM_TOTAL);
        attr_done = true;
    }

    pe_kernel<<<(SEQ_LEN * FEAT + 255) / 256, 256>>>();
    pack_x_kernel<<<(N_FRAMES * FEAT + 255) / 256, 256>>>(sup, qry);
    pack_wt_kernel<<<dim3(WCOLS / 32, FEAT / 32), dim3(32, 8)>>>(kw, vw);
    zero_dist_kernel<<<(WAY * NQ + 255) / 256, 256>>>();

    // frame partials: [4200,2048] @ [4608,2048]^T
    mma_gemm<0><<<dim3(WCOLS / BN, (N_FRAMES + BM - 1) / BM), 256, SM_TOTAL>>>(
        pX, pWT, pP, N_FRAMES, WCOLS, FEAT, FEAT, FEAT, WCOLS, 1.0f);

    combine_ln_kernel<<<N_CLIPS * T_LEN, 256>>>(kb, vb, gamma, beta);

    // scores: [14000,1152] @ [700,1152]^T, scaled by 1/sqrt(1152)
    mma_gemm<1><<<dim3((SROWS + BN - 1) / BN, (QROWS + BM - 1) / BM), 256, SM_TOTAL>>>(
        pQK, pSK, pS, QROWS, SROWS, DOUT, DOUT, DOUT, SROWS,
        0.029462782549439484f);

    softmax_kernel<<<(QROWS * WAY * 32 + 255) / 256, 256>>>();

    // proto + fused distance: per class, attn[14000,140] @ svT[1152,140]^T
    mma_gemm<2><<<dim3((DOUT + BN - 1) / BN, (QROWS + BM - 1) / BM, WAY), 256, SM_TOTAL>>>(
        pS, pSVT, nullptr, QROWS, DOUT, KU, SROWS, KU, 0, 1.0f);

    final_kernel<<<(NQ * WAY + 255) / 256, 256>>>(gt, tw, out);
}

// round 15
// speedup vs baseline: 5.2973x; 1.5452x over previous
#include <cuda_runtime.h>
#include <cuda_bf16.h>
#include <math.h>
#include <stdint.h>

// ---------------------------------------------------------------------------
// Problem constants
// ---------------------------------------------------------------------------
#define SEQ_LEN   8
#define FEAT      2048
#define DOUT      1152
#define WAY       5
#define SHOT      5
#define NQ        500
#define T_LEN     28
#define N_SUP     (WAY * SHOT)           // 25
#define N_CLIPS   (N_SUP + NQ)           // 525
#define N_FRAMES  (N_CLIPS * SEQ_LEN)    // 4200
#define WCOLS     (4 * DOUT)             // 4608
#define SROWS     (N_SUP * T_LEN)        // 700
#define QROWS     (NQ * T_LEN)           // 14000
#define KU        (SHOT * T_LEN)         // 140
#define KUP       144                    // KU padded to 16B-aligned bf16 rows
#define LN_EPS    1e-5f

// bf16 mma tile config
#define BM 128
#define BN 128
#define BK 64
#define PADH 72                                  // smem row stride (halves)
#define STG_HALFS ((BM + BN) * PADH)             // 18432 halves / stage
#define SM_TOTAL (2 * STG_HALFS * 2)             // 2 stages -> 73728 bytes

__constant__ int2 c_tup[T_LEN] = {
    {0,1},{0,2},{0,3},{0,4},{0,5},{0,6},{0,7},
    {1,2},{1,3},{1,4},{1,5},{1,6},{1,7},
    {2,3},{2,4},{2,5},{2,6},{2,7},
    {3,4},{3,5},{3,6},{3,7},
    {4,5},{4,6},{4,7},
    {5,6},{5,7},
    {6,7}
};

// ---------------------------------------------------------------------------
// Device scratch (allocation-free per harness rules)
// ---------------------------------------------------------------------------
__device__ float          g_PE[SEQ_LEN * FEAT];
__device__ __nv_bfloat16  g_X[N_FRAMES * FEAT];          // frames + PE
__device__ __nv_bfloat16  g_WT[WCOLS * FEAT];            // packed W, K-major
__device__ float          g_P[N_FRAMES * WCOLS];         // frame partials (fp32)
__device__ __nv_bfloat16  g_sk[SROWS * DOUT];            // support K (LN'd)
__device__ __nv_bfloat16  g_svT[WAY * DOUT * KUP];       // support V^T, padded rows
__device__ __nv_bfloat16  g_qk[QROWS * DOUT];            // query K (LN'd)
__device__ float          g_qv[QROWS * DOUT];            // query V (fp32)
__device__ float          g_S[QROWS * SROWS];            // scores (fp32)
__device__ __nv_bfloat16  g_attn[WAY * QROWS * KUP];     // attn per-class planes
__device__ float          g_dist[WAY * NQ];

// ---------------------------------------------------------------------------
// PTX helpers (baseline ISA only -- harness targets compute_103, no tcgen05)
// ---------------------------------------------------------------------------
__device__ __forceinline__ uint32_t smem_u32(const void* p) {
    uint32_t a;
    asm("{ .reg .u64 t; cvta.to.shared.u64 t, %1; cvt.u32.u64 %0, t; }" : "=r"(a) : "l"(p));
    return a;
}
__device__ __forceinline__ void cp_async16(uint32_t dst, const void* src, int sz) {
    asm volatile("cp.async.cg.shared.global [%0], [%1], 16, %2;"
                 :: "r"(dst), "l"(src), "r"(sz) : "memory");
}
__device__ __forceinline__ void cp_commit() {
    asm volatile("cp.async.commit_group;" ::: "memory");
}
template<int N>
__device__ __forceinline__ void cp_wait() {
    asm volatile("cp.async.wait_group %0;" :: "n"(N) : "memory");
}

// D += A@B, one m16n8k16 bf16 tile (fp32 accumulate)
__device__ __forceinline__ void mma_bf16(float* c, const uint32_t* a, const uint32_t* b) {
    asm volatile(
        "mma.sync.aligned.m16n8k16.row.col.f32.bf16.bf16.f32 "
        "{%0,%1,%2,%3}, {%4,%5,%6,%7}, {%8,%9}, {%0,%1,%2,%3};"
        : "+f"(c[0]), "+f"(c[1]), "+f"(c[2]), "+f"(c[3])
        : "r"(a[0]), "r"(a[1]), "r"(a[2]), "r"(a[3]), "r"(b[0]), "r"(b[1]));
}

// ---------------------------------------------------------------------------
// K0pe: positional-encoding table [8, 2048]
// ---------------------------------------------------------------------------
__global__ void pe_kernel()
{
    int idx = blockIdx.x * blockDim.x + threadIdx.x;
    if (idx >= SEQ_LEN * FEAT) return;
    int d = idx & (FEAT - 1);
    int f = idx >> 11;
    const float c = -9.210340371976184f / 2048.0f;
    int  i2  = d >> 1;
    float dv = expf((float)(2 * i2) * c);
    float arg = (float)f * dv;
    g_PE[idx] = (d & 1) ? cosf(arg) : sinf(arg);
}

// ---------------------------------------------------------------------------
// K0a: X = frames + PE (bf16)
// ---------------------------------------------------------------------------
__global__ void pack_x_kernel(const float* __restrict__ sup,
                              const float* __restrict__ qry)
{
    int idx = blockIdx.x * blockDim.x + threadIdx.x;
    if (idx >= N_FRAMES * FEAT) return;
    int d   = idx & (FEAT - 1);
    int row = idx >> 11;
    int f   = row & 7;
    float pe = g_PE[f * FEAT + d];
    float x = (row < N_SUP * SEQ_LEN) ? sup[idx] : qry[idx - N_SUP * SEQ_LEN * FEAT];
    g_X[idx] = __float2bfloat16_rn(x + pe);
}

// ---------------------------------------------------------------------------
// K0b: WT[n,k] = W_packed[k,n], tiled transpose -> bf16
// ---------------------------------------------------------------------------
__global__ void pack_wt_kernel(const float* __restrict__ kw,
                               const float* __restrict__ vw)
{
    __shared__ float t[32][33];
    int n0 = blockIdx.x * 32;
    int k0 = blockIdx.y * 32;
    int tx = threadIdx.x, ty = threadIdx.y;   // 32x8

    int blk = n0 / DOUT;
    const float* src = (blk < 2) ? kw : vw;
    int half = blk & 1;
    int jj0  = n0 - blk * DOUT;

#pragma unroll
    for (int i = 0; i < 4; i++) {
        int k = k0 + ty + i * 8;
        t[ty + i * 8][tx] = src[(size_t)(half * FEAT + k) * DOUT + jj0 + tx];
    }
    __syncthreads();
#pragma unroll
    for (int i = 0; i < 4; i++) {
        int n = n0 + ty + i * 8;
        g_WT[(size_t)n * FEAT + k0 + tx] = __float2bfloat16_rn(t[tx][ty + i * 8]);
    }
}

// zero g_dist + entire g_svT (so KUP pads stay zero; combine writes real cols)
#define SVT_ELEMS (WAY * DOUT * KUP)
__global__ void zero_kernel()
{
    int idx = blockIdx.x * blockDim.x + threadIdx.x;
    if (idx < WAY * NQ) g_dist[idx] = 0.0f;
    if (idx < SVT_ELEMS) g_svT[idx] = __float2bfloat16_rn(0.0f);
}

// ---------------------------------------------------------------------------
// bf16 mma.sync GEMM: C[M,N] = A[M,K] @ B[N,K]^T (both K-major bf16).
// 128x128x64 block tile, 8 warps (4M x 2N), warp tile 32x64, 2-stage cp.async.
// MODE 0: store C (fp32).  MODE 1: store C*scale w/ col guard.
// MODE 2: fused (qv-C)^2 row-reduction -> atomicAdd g_dist; blockIdx.z=class.
// ---------------------------------------------------------------------------
template<int MODE>
__global__ void __launch_bounds__(256, 2)
mma_gemm(const __nv_bfloat16* __restrict__ Ain, const __nv_bfloat16* __restrict__ Bin,
         float* __restrict__ C, int M, int N, int K,
         int lda, int ldb, int ldc, float scale)
{
    extern __shared__ __nv_bfloat16 sm[];
    int tid  = threadIdx.x;
    int wid  = tid >> 5, lane = tid & 31;
    int gid  = lane >> 2, tig = lane & 3;
    int wy   = wid & 3,  wx  = wid >> 2;
    int mBase = blockIdx.y * BM;
    int nBase = blockIdx.x * BN;

    const __nv_bfloat16* A = Ain;
    const __nv_bfloat16* B = Bin;
    int cls = 0;
    if (MODE == 2) {
        cls = blockIdx.z;
        A += (size_t)cls * QROWS * KUP;       // attn plane, lda = KUP
        B += (size_t)cls * DOUT * KUP;        // svT class block, ldb = KUP
    }

    float acc[2][8][4];
#pragma unroll
    for (int i = 0; i < 2; i++)
#pragma unroll
        for (int j = 0; j < 8; j++)
#pragma unroll
            for (int l = 0; l < 4; l++) acc[i][j][l] = 0.f;

    const int nIter = (K + BK - 1) / BK;
    uint32_t sbase = smem_u32(sm);

    // stage loader: A tile [128 x 64] + B tile [128 x 64] bf16, 16B cp.async
    auto load_stage = [&](int it, int s) {
        int k0 = it * BK;
        uint32_t stg = sbase + (uint32_t)s * (STG_HALFS * 2);
#pragma unroll
        for (int p = 0; p < 4; p++) {
            int i = tid + p * 256;
            int r = i >> 3, seg = i & 7;
            int gr = mBase + r, gk = k0 + seg * 8;
            int ok = (gr < M) & (gk < K);
            const __nv_bfloat16* src = ok ? (A + (size_t)gr * lda + gk) : A;
            cp_async16(stg + (uint32_t)(r * PADH + seg * 8) * 2, src, ok ? 16 : 0);
        }
#pragma unroll
        for (int p = 0; p < 4; p++) {
            int i = tid + p * 256;
            int r = i >> 3, seg = i & 7;
            int gn = nBase + r, gk = k0 + seg * 8;
            int ok = (gn < N) & (gk < K);
            const __nv_bfloat16* src = ok ? (B + (size_t)gn * ldb + gk) : B;
            cp_async16(stg + (uint32_t)(BM * PADH + r * PADH + seg * 8) * 2, src, ok ? 16 : 0);
        }
        cp_commit();
    };

    load_stage(0, 0);

    for (int it = 0; it < nIter; it++) {
        bool more = (it + 1 < nIter);
        if (more) load_stage(it + 1, (it + 1) & 1);
        if (more) cp_wait<1>(); else cp_wait<0>();
        __syncthreads();

        const __nv_bfloat16* As = sm + (it & 1) * STG_HALFS;
        const __nv_bfloat16* Bs = As + BM * PADH;

#pragma unroll
        for (int kk = 0; kk < BK; kk += 16) {
            uint32_t af[2][4];
            uint32_t bf[8][2];
#pragma unroll
            for (int mt = 0; mt < 2; mt++) {
                const __nv_bfloat16* pa = As + (wy * 32 + mt * 16 + gid) * PADH + kk + 2 * tig;
                af[mt][0] = *(const uint32_t*)(pa);
                af[mt][1] = *(const uint32_t*)(pa + 8 * PADH);
                af[mt][2] = *(const uint32_t*)(pa + 8);
                af[mt][3] = *(const uint32_t*)(pa + 8 * PADH + 8);
            }
#pragma unroll
            for (int nt = 0; nt < 8; nt++) {
                const __nv_bfloat16* pb = Bs + (wx * 64 + nt * 8 + gid) * PADH + kk + 2 * tig;
                bf[nt][0] = *(const uint32_t*)(pb);
                bf[nt][1] = *(const uint32_t*)(pb + 8);
            }
#pragma unroll
            for (int mt = 0; mt < 2; mt++)
#pragma unroll
                for (int nt = 0; nt < 8; nt++)
                    mma_bf16(acc[mt][nt], af[mt], bf[nt]);
        }
        __syncthreads();
    }

    // ------------------------------------------------------------ epilogue
    if (MODE == 2) {
        float* rowsum = (float*)sm;               // reuse smem (post-sync)
        if (tid < BM) rowsum[tid] = 0.f;
        __syncthreads();
#pragma unroll
        for (int mt = 0; mt < 2; mt++) {
#pragma unroll
            for (int h = 0; h < 2; h++) {
                int rloc = wy * 32 + mt * 16 + gid + 8 * h;
                int gr = mBase + rloc;
                if (gr < M) {
                    float s = 0.f;
#pragma unroll
                    for (int nt = 0; nt < 8; nt++) {
                        int gc = nBase + wx * 64 + nt * 8 + tig * 2;
                        float2 q = *(const float2*)(g_qv + (size_t)gr * DOUT + gc);
                        float d0 = q.x - acc[mt][nt][2 * h];
                        float d1 = q.y - acc[mt][nt][2 * h + 1];
                        s += d0 * d0 + d1 * d1;
                    }
                    atomicAdd(&rowsum[rloc], s);
                }
            }
        }
        __syncthreads();
        if (tid < BM) {
            int gr = mBase + tid;
            if (gr < M) atomicAdd(&g_dist[cls * NQ + gr / T_LEN], rowsum[tid]);
        }
    } else {
#pragma unroll
        for (int mt = 0; mt < 2; mt++) {
#pragma unroll
            for (int h = 0; h < 2; h++) {
                int gr = mBase + wy * 32 + mt * 16 + gid + 8 * h;
                if (gr >= M) continue;
                float* crow = C + (size_t)gr * ldc;
#pragma unroll
                for (int nt = 0; nt < 8; nt++) {
                    int gc = nBase + wx * 64 + nt * 8 + tig * 2;
                    if (MODE == 1 && gc >= N) continue;  // N even, pair-safe
                    float2 v;
                    v.x = acc[mt][nt][2 * h] * scale;
                    v.y = acc[mt][nt][2 * h + 1] * scale;
                    *(float2*)(crow + gc) = v;
                }
            }
        }
    }
}

// ---------------------------------------------------------------------------
// K2: combine frame partials + bias; LN on K path (outputs bf16; qv fp32).
// ---------------------------------------------------------------------------
__global__ void __launch_bounds__(256)
combine_ln_kernel(const float* __restrict__ kb, const float* __restrict__ vb,
                  const float* __restrict__ gamma, const float* __restrict__ beta)
{
    __shared__ float buf[DOUT];
    __shared__ float rs[8], rq[8];

    int r = blockIdx.x;
    int n = r / T_LEN;
    int t = r - n * T_LEN;
    int2 tp = c_tup[t];

    const float* pi = g_P + (size_t)(n * SEQ_LEN + tp.x) * WCOLS;
    const float* pj = g_P + (size_t)(n * SEQ_LEN + tp.y) * WCOLS;

    __nv_bfloat16* kout;
    float* qvout = nullptr;
    __nv_bfloat16* svTout = nullptr;
    if (n < N_SUP) {
        kout = g_sk + (size_t)r * DOUT;
        int c  = n / SHOT;
        int ku = (n - c * SHOT) * T_LEN + t;
        svTout = g_svT + (size_t)c * DOUT * KUP + ku;    // + d*KUP per element
    } else {
        size_t qr = (size_t)(r - SROWS) * DOUT;
        kout  = g_qk + qr;
        qvout = g_qv + qr;
    }

    int tid = threadIdx.x;
    float s = 0.f, sq = 0.f;
    for (int d = tid; d < DOUT; d += 256) {
        float kv = pi[d] + pj[DOUT + d] + kb[d];
        buf[d] = kv;
        s += kv; sq += kv * kv;
        float vv = pi[2 * DOUT + d] + pj[3 * DOUT + d] + vb[d];
        if (qvout) qvout[d] = vv;
        else       svTout[(size_t)d * KUP] = __float2bfloat16_rn(vv);
    }
#pragma unroll
    for (int o = 16; o; o >>= 1) {
        s  += __shfl_xor_sync(0xffffffffu, s, o);
        sq += __shfl_xor_sync(0xffffffffu, sq, o);
    }
    int lane = tid & 31, wid = tid >> 5;
    if (lane == 0) { rs[wid] = s; rq[wid] = sq; }
    __syncthreads();
    if (tid == 0) {
        float S = 0.f, Q = 0.f;
#pragma unroll
        for (int w = 0; w < 8; w++) { S += rs[w]; Q += rq[w]; }
        rs[0] = S; rq[0] = Q;
    }
    __syncthreads();
    float mean = rs[0] * (1.0f / DOUT);
    float var  = rq[0] * (1.0f / DOUT) - mean * mean;
    float rstd = rsqrtf(var + LN_EPS);
    for (int d = tid; d < DOUT; d += 256)
        kout[d] = __float2bfloat16_rn((buf[d] - mean) * rstd * gamma[d] + beta[d]);
}

// ---------------------------------------------------------------------------
// K4: softmax over 140-chunks; writes bf16 attn into per-class planes
// (row stride KUP=144, pads [140,144) zeroed for the proto GEMM).
// ---------------------------------------------------------------------------
__global__ void softmax_kernel()
{
    int warp = (blockIdx.x * blockDim.x + threadIdx.x) >> 5;
    if (warp >= QROWS * WAY) return;
    int lane = threadIdx.x & 31;
    int row = warp / WAY;
    int c   = warp - row * WAY;
    const float* p = g_S + (size_t)row * SROWS + c * KU;
    __nv_bfloat16* po = g_attn + ((size_t)c * QROWS + row) * KUP;

    float v[5];
    float mx = -1e30f;
#pragma unroll
    for (int l = 0; l < 5; l++) {
        int idx = lane + 32 * l;
        v[l] = (idx < KU) ? p[idx] : -1e30f;
        mx = fmaxf(mx, v[l]);
    }
#pragma unroll
    for (int o = 16; o; o >>= 1) mx = fmaxf(mx, __shfl_xor_sync(0xffffffffu, mx, o));
    float s = 0.f;
#pragma unroll
    for (int l = 0; l < 5; l++) {
        int idx = lane + 32 * l;
        v[l] = (idx < KU) ? expf(v[l] - mx) : 0.f;
        s += v[l];
    }
#pragma unroll
    for (int o = 16; o; o >>= 1) s += __shfl_xor_sync(0xffffffffu, s, o);
    float inv = 1.0f / s;
#pragma unroll
    for (int l = 0; l < 5; l++) {
        int idx = lane + 32 * l;
        if (idx < KU)       po[idx] = __float2bfloat16_rn(v[l] * inv);
        else if (idx < KUP) po[idx] = __float2bfloat16_rn(0.0f);
    }
}

// ---------------------------------------------------------------------------
// K6: logits[q, c]
// ---------------------------------------------------------------------------
__global__ void final_kernel(const float* __restrict__ gt,
                             const float* __restrict__ tw,
                             float* __restrict__ out)
{
    int idx = blockIdx.x * blockDim.x + threadIdx.x;
    if (idx >= NQ * WAY) return;
    int q = idx / WAY;
    int c = idx - q * WAY;
    out[idx] = -(g_dist[c * NQ + q] * (1.0f / T_LEN)) * gt[0] * tw[0];
}

// ---------------------------------------------------------------------------
// launcher
// ---------------------------------------------------------------------------
extern "C" void kernel_launch(void* const* d_in, const int* in_sizes, int n_in,
                              void* d_out, int out_size)
{
    const float* sup   = (const float*)d_in[0];
    // d_in[1] = support_labels (sorted & balanced -> implicit reshape)
    const float* qry   = (const float*)d_in[2];
    const float* kw    = (const float*)d_in[3];
    const float* kb    = (const float*)d_in[4];
    const float* vw    = (const float*)d_in[5];
    const float* vb    = (const float*)d_in[6];
    const float* gamma = (const float*)d_in[7];
    const float* beta  = (const float*)d_in[8];
    const float* gt    = (const float*)d_in[9];
    const float* tw    = (const float*)d_in[10];
    float* out = (float*)d_out;

    __nv_bfloat16 *pX, *pWT, *pSK, *pSVT, *pQK, *pAT;
    float *pP, *pS;
    cudaGetSymbolAddress((void**)&pX,  g_X);
    cudaGetSymbolAddress((void**)&pWT, g_WT);
    cudaGetSymbolAddress((void**)&pP,  g_P);
    cudaGetSymbolAddress((void**)&pSK, g_sk);
    cudaGetSymbolAddress((void**)&pSVT, g_svT);
    cudaGetSymbolAddress((void**)&pQK, g_qk);
    cudaGetSymbolAddress((void**)&pS,  g_S);
    cudaGetSymbolAddress((void**)&pAT, g_attn);

    static bool attr_done = false;
    if (!attr_done) {
        cudaFuncSetAttribute(mma_gemm<0>, cudaFuncAttributeMaxDynamicSharedMemorySize, SM_TOTAL);
        cudaFuncSetAttribute(mma_gemm<1>, cudaFuncAttributeMaxDynamicSharedMemorySize, SM_TOTAL);
        cudaFuncSetAttribute(mma_gemm<2>, cudaFuncAttributeMaxDynamicSharedMemorySize, SM_TOTAL);
        attr_done = true;
    }

    pe_kernel<<<(SEQ_LEN * FEAT + 255) / 256, 256>>>();
    pack_x_kernel<<<(N_FRAMES * FEAT + 255) / 256, 256>>>(sup, qry);
    pack_wt_kernel<<<dim3(WCOLS / 32, FEAT / 32), dim3(32, 8)>>>(kw, vw);
    zero_kernel<<<(SVT_ELEMS + 255) / 256, 256>>>();

    // frame partials: [4200,2048] @ [4608,2048]^T -> fp32
    mma_gemm<0><<<dim3(WCOLS / BN, (N_FRAMES + BM - 1) / BM), 256, SM_TOTAL>>>(
        pX, pWT, pP, N_FRAMES, WCOLS, FEAT, FEAT, FEAT, WCOLS, 1.0f);

    combine_ln_kernel<<<N_CLIPS * T_LEN, 256>>>(kb, vb, gamma, beta);

    // scores: [14000,1152] @ [700,1152]^T, scaled by 1/sqrt(1152) -> fp32
    mma_gemm<1><<<dim3((SROWS + BN - 1) / BN, (QROWS + BM - 1) / BM), 256, SM_TOTAL>>>(
        pQK, pSK, pS, QROWS, SROWS, DOUT, DOUT, DOUT, SROWS,
        0.029462782549439484f);

    softmax_kernel<<<(QROWS * WAY * 32 + 255) / 256, 256>>>();

    // proto + fused distance: per class, attn[14000,144] @ svT[1152,144]^T
    // (K=144: pads are zero on both sides, so extra terms vanish)
    mma_gemm<2><<<dim3((DOUT + BN - 1) / BN, (QROWS + BM - 1) / BM, WAY), 256, SM_TOTAL>>>(
        pAT, pSVT, nullptr, QROWS, DOUT, KUP, KUP, KUP, 0, 1.0f);

    final_kernel<<<(NQ * WAY + 255) / 256, 256>>>(gt, tw, out);
}